// round 3
// baseline (speedup 1.0000x reference)
#include <cuda_runtime.h>
#include <math.h>

// ---------------------------------------------------------------------------
// SlatewiseGRU: N=8192 sequences, L=32 steps, D=128, gates 3D=384.
// Fused single kernel: per step, register-blocked GEMM (x-side + h-side) with
// packed fp32x2 FMAs, gate nonlinearity + h update + W_out projection in the
// epilogue. Weights pre-transposed into __device__ scratch for coalesced,
// L1-resident loads.
// ---------------------------------------------------------------------------

#define DD   128
#define LL   32
#define NSEQ 8192
#define G3   384
#define TN   64      // sequences per CTA
#define NTHR 512     // 16 warps: warp -> 4 seqs, lane -> 4 units
#define NCTA (NSEQ / TN)  // 128

typedef unsigned long long ull;

// Transposed weights: Wt[k][j] = W[j][k], k in [0,128), j in [0,384)
__device__ float g_wt_ih[DD * G3];
__device__ float g_wt_hh[DD * G3];

__global__ void prep_weights(const float* __restrict__ W_ih,
                             const float* __restrict__ W_hh) {
    int i = blockIdx.x * blockDim.x + threadIdx.x;
    if (i < DD * G3) {
        int k = i / G3;
        int j = i % G3;
        g_wt_ih[i] = W_ih[j * DD + k];
        g_wt_hh[i] = W_hh[j * DD + k];
    }
}

__device__ __forceinline__ ull fma2(ull a, ull b, ull c) {
    ull d;
    asm("fma.rn.f32x2 %0, %1, %2, %3;" : "=l"(d) : "l"(a), "l"(b), "l"(c));
    return d;
}
__device__ __forceinline__ ull pack2(float x) {  // {x, x}
    ull d;
    asm("mov.b64 %0, {%1, %1};" : "=l"(d) : "f"(x));
    return d;
}
__device__ __forceinline__ float lo2(ull a) { return __uint_as_float((unsigned)a); }
__device__ __forceinline__ float hi2(ull a) { return __uint_as_float((unsigned)(a >> 32)); }

extern __shared__ float sm[];  // Ax[TN*DD] | Ah[TN*DD] | bias[2*G3]

__global__ void __launch_bounds__(NTHR, 1)
gru_kernel(const float* __restrict__ item,   // [N, L, D]
           const float* __restrict__ user,   // [N, D]
           const float* __restrict__ b_ih,   // [384]
           const float* __restrict__ b_hh,   // [384]
           const float* __restrict__ W_out,  // [1, 128]
           const float* __restrict__ b_out,  // [1]
           float* __restrict__ out)          // [N, L]
{
    float* Ax = sm;                // x_t, [seq][128]
    float* Ah = sm + TN * DD;      // h,   [seq][128]
    float* Bs = sm + 2 * TN * DD;  // b_ih[0:384], b_hh[384:768]

    const int tid   = threadIdx.x;
    const int w     = tid >> 5;
    const int l     = tid & 31;
    const int nBase = blockIdx.x * TN;
    const int sB    = w * 4;   // this thread's 4 sequences (local)
    const int u0    = l * 4;   // this thread's 4 hidden units

    // Biases into smem (read every epilogue).
    for (int i = tid; i < 2 * G3; i += NTHR)
        Bs[i] = (i < G3) ? b_ih[i] : b_hh[i - G3];

    // h0 = user_embs rows (contiguous [N,D] slab -> flat float4 copy).
    {
        const float4* src = (const float4*)(user + (size_t)nBase * DD);
        float4* dst = (float4*)Ah;
        for (int i = tid; i < TN * DD / 4; i += NTHR) dst[i] = src[i];
    }

    const float4 wo = *(const float4*)(W_out + u0);
    const float  bo = b_out[0];

    // acc[seq][gate: r,z,n_x,n_h][unit-pair], packed f32x2
    ull acc[4][4][2];

    for (int t = 0; t < LL; ++t) {
        // ---- stage x_t into smem (coalesced: lane = d-chunk) ----
        for (int i = tid; i < TN * DD / 4; i += NTHR) {
            int seq = i >> 5;   // 32 float4 per row
            int c   = i & 31;
            ((float4*)Ax)[i] =
                *(const float4*)(item + ((size_t)(nBase + seq) * LL + t) * DD + c * 4);
        }
        __syncthreads();  // x_t visible; prev-step Ah writes visible

        #pragma unroll
        for (int s = 0; s < 4; ++s)
            #pragma unroll
            for (int g = 0; g < 4; ++g)
                #pragma unroll
                for (int p = 0; p < 2; ++p)
                    acc[s][g][p] = 0ull;

        // ---- GEMM: K=128, x-side (W_ih) + h-side (W_hh) fused ----
        #pragma unroll 2
        for (int k = 0; k < DD; ++k) {
            const float* wik = g_wt_ih + k * G3;
            const float* whk = g_wt_hh + k * G3;
            ulonglong2 wir = *(const ulonglong2*)(wik + u0);
            ulonglong2 wiz = *(const ulonglong2*)(wik + 128 + u0);
            ulonglong2 win = *(const ulonglong2*)(wik + 256 + u0);
            ulonglong2 whr = *(const ulonglong2*)(whk + u0);
            ulonglong2 whz = *(const ulonglong2*)(whk + 128 + u0);
            ulonglong2 whn = *(const ulonglong2*)(whk + 256 + u0);
            #pragma unroll
            for (int s = 0; s < 4; ++s) {
                ull x2 = pack2(Ax[(sB + s) * DD + k]);  // broadcast LDS
                ull h2 = pack2(Ah[(sB + s) * DD + k]);
                acc[s][0][0] = fma2(x2, wir.x, acc[s][0][0]);
                acc[s][0][1] = fma2(x2, wir.y, acc[s][0][1]);
                acc[s][0][0] = fma2(h2, whr.x, acc[s][0][0]);
                acc[s][0][1] = fma2(h2, whr.y, acc[s][0][1]);
                acc[s][1][0] = fma2(x2, wiz.x, acc[s][1][0]);
                acc[s][1][1] = fma2(x2, wiz.y, acc[s][1][1]);
                acc[s][1][0] = fma2(h2, whz.x, acc[s][1][0]);
                acc[s][1][1] = fma2(h2, whz.y, acc[s][1][1]);
                acc[s][2][0] = fma2(x2, win.x, acc[s][2][0]);
                acc[s][2][1] = fma2(x2, win.y, acc[s][2][1]);
                acc[s][3][0] = fma2(h2, whn.x, acc[s][3][0]);
                acc[s][3][1] = fma2(h2, whn.y, acc[s][3][1]);
            }
        }
        __syncthreads();  // all GEMM reads of Ax/Ah complete

        // ---- epilogue: gates, h update (owned cells only), output dot ----
        #pragma unroll
        for (int s = 0; s < 4; ++s) {
            float hn[4];
            #pragma unroll
            for (int p = 0; p < 2; ++p) {
                #pragma unroll
                for (int half = 0; half < 2; ++half) {
                    int   uu = u0 + p * 2 + half;
                    float ar = half ? hi2(acc[s][0][p]) : lo2(acc[s][0][p]);
                    float az = half ? hi2(acc[s][1][p]) : lo2(acc[s][1][p]);
                    float axn = half ? hi2(acc[s][2][p]) : lo2(acc[s][2][p]);
                    float ahn = half ? hi2(acc[s][3][p]) : lo2(acc[s][3][p]);
                    float r = 1.f / (1.f + expf(-(ar + Bs[uu] + Bs[G3 + uu])));
                    float z = 1.f / (1.f + expf(-(az + Bs[128 + uu] + Bs[G3 + 128 + uu])));
                    float n = tanhf(axn + Bs[256 + uu] + r * (ahn + Bs[G3 + 256 + uu]));
                    float hold = Ah[(sB + s) * DD + uu];
                    hn[p * 2 + half] = (1.f - z) * n + z * hold;
                }
            }
            *(float4*)(Ah + (sB + s) * DD + u0) =
                make_float4(hn[0], hn[1], hn[2], hn[3]);

            float dot = hn[0] * wo.x + hn[1] * wo.y + hn[2] * wo.z + hn[3] * wo.w;
            #pragma unroll
            for (int off = 16; off; off >>= 1)
                dot += __shfl_xor_sync(0xffffffffu, dot, off);
            if (l == 0)
                out[(size_t)(nBase + sB + s) * LL + t] = dot + bo;
        }
        // no extra sync needed: next iter's post-load __syncthreads orders
        // these Ah writes before the next GEMM's reads.
    }
}

extern "C" void kernel_launch(void* const* d_in, const int* in_sizes, int n_in,
                              void* d_out, int out_size) {
    const float* item  = (const float*)d_in[0];
    const float* user  = (const float*)d_in[1];
    const float* W_ih  = (const float*)d_in[2];
    const float* W_hh  = (const float*)d_in[3];
    const float* b_ih  = (const float*)d_in[4];
    const float* b_hh  = (const float*)d_in[5];
    const float* W_out = (const float*)d_in[6];
    const float* b_out = (const float*)d_in[7];
    float* out = (float*)d_out;

    prep_weights<<<(DD * G3 + 255) / 256, 256>>>(W_ih, W_hh);

    size_t smem = (size_t)(2 * TN * DD + 2 * G3) * sizeof(float);  // 68.6 KB
    cudaFuncSetAttribute(gru_kernel,
                         cudaFuncAttributeMaxDynamicSharedMemorySize, (int)smem);
    gru_kernel<<<NCTA, NTHR, smem>>>(item, user, b_ih, b_hh, W_out, b_out, out);
}

// round 4
// speedup vs baseline: 1.0023x; 1.0023x over previous
#include <cuda_runtime.h>
#include <math.h>

// ---------------------------------------------------------------------------
// SlatewiseGRU: N=8192 sequences, L=32 steps, D=128, gates 3D=384.
// Fused single kernel: per step, register-blocked GEMM (x-side + h-side) with
// packed fp32x2 FMAs, gate nonlinearity + h update + W_out projection in the
// epilogue. Weights pre-transposed into __device__ scratch for coalesced,
// L1-resident loads.
// ---------------------------------------------------------------------------

#define DD   128
#define LL   32
#define NSEQ 8192
#define G3   384
#define TN   64      // sequences per CTA
#define NTHR 512     // 16 warps: warp -> 4 seqs, lane -> 4 units
#define NCTA (NSEQ / TN)  // 128

typedef unsigned long long ull;

// Transposed weights: Wt[k][j] = W[j][k], k in [0,128), j in [0,384)
__device__ float g_wt_ih[DD * G3];
__device__ float g_wt_hh[DD * G3];

__global__ void prep_weights(const float* __restrict__ W_ih,
                             const float* __restrict__ W_hh) {
    int i = blockIdx.x * blockDim.x + threadIdx.x;
    if (i < DD * G3) {
        int k = i / G3;
        int j = i % G3;
        g_wt_ih[i] = W_ih[j * DD + k];
        g_wt_hh[i] = W_hh[j * DD + k];
    }
}

__device__ __forceinline__ ull fma2(ull a, ull b, ull c) {
    ull d;
    asm("fma.rn.f32x2 %0, %1, %2, %3;" : "=l"(d) : "l"(a), "l"(b), "l"(c));
    return d;
}
__device__ __forceinline__ ull pack2(float x) {  // {x, x}
    ull d;
    asm("mov.b64 %0, {%1, %1};" : "=l"(d) : "f"(x));
    return d;
}
__device__ __forceinline__ float lo2(ull a) { return __uint_as_float((unsigned)a); }
__device__ __forceinline__ float hi2(ull a) { return __uint_as_float((unsigned)(a >> 32)); }

extern __shared__ float sm[];  // Ax[TN*DD] | Ah[TN*DD] | bias[2*G3]

__global__ void __launch_bounds__(NTHR, 1)
gru_kernel(const float* __restrict__ item,   // [N, L, D]
           const float* __restrict__ user,   // [N, D]
           const float* __restrict__ b_ih,   // [384]
           const float* __restrict__ b_hh,   // [384]
           const float* __restrict__ W_out,  // [1, 128]
           const float* __restrict__ b_out,  // [1]
           float* __restrict__ out)          // [N, L]
{
    float* Ax = sm;                // x_t, [seq][128]
    float* Ah = sm + TN * DD;      // h,   [seq][128]
    float* Bs = sm + 2 * TN * DD;  // b_ih[0:384], b_hh[384:768]

    const int tid   = threadIdx.x;
    const int w     = tid >> 5;
    const int l     = tid & 31;
    const int nBase = blockIdx.x * TN;
    const int sB    = w * 4;   // this thread's 4 sequences (local)
    const int u0    = l * 4;   // this thread's 4 hidden units

    // Biases into smem (read every epilogue).
    for (int i = tid; i < 2 * G3; i += NTHR)
        Bs[i] = (i < G3) ? b_ih[i] : b_hh[i - G3];

    // h0 = user_embs rows (contiguous [N,D] slab -> flat float4 copy).
    {
        const float4* src = (const float4*)(user + (size_t)nBase * DD);
        float4* dst = (float4*)Ah;
        for (int i = tid; i < TN * DD / 4; i += NTHR) dst[i] = src[i];
    }

    const float4 wo = *(const float4*)(W_out + u0);
    const float  bo = b_out[0];

    // acc[seq][gate: r,z,n_x,n_h][unit-pair], packed f32x2
    ull acc[4][4][2];

    for (int t = 0; t < LL; ++t) {
        // ---- stage x_t into smem (coalesced: lane = d-chunk) ----
        for (int i = tid; i < TN * DD / 4; i += NTHR) {
            int seq = i >> 5;   // 32 float4 per row
            int c   = i & 31;
            ((float4*)Ax)[i] =
                *(const float4*)(item + ((size_t)(nBase + seq) * LL + t) * DD + c * 4);
        }
        __syncthreads();  // x_t visible; prev-step Ah writes visible

        #pragma unroll
        for (int s = 0; s < 4; ++s)
            #pragma unroll
            for (int g = 0; g < 4; ++g)
                #pragma unroll
                for (int p = 0; p < 2; ++p)
                    acc[s][g][p] = 0ull;

        // ---- GEMM: K=128, x-side (W_ih) + h-side (W_hh) fused ----
        #pragma unroll 2
        for (int k = 0; k < DD; ++k) {
            const float* wik = g_wt_ih + k * G3;
            const float* whk = g_wt_hh + k * G3;
            ulonglong2 wir = *(const ulonglong2*)(wik + u0);
            ulonglong2 wiz = *(const ulonglong2*)(wik + 128 + u0);
            ulonglong2 win = *(const ulonglong2*)(wik + 256 + u0);
            ulonglong2 whr = *(const ulonglong2*)(whk + u0);
            ulonglong2 whz = *(const ulonglong2*)(whk + 128 + u0);
            ulonglong2 whn = *(const ulonglong2*)(whk + 256 + u0);
            #pragma unroll
            for (int s = 0; s < 4; ++s) {
                ull x2 = pack2(Ax[(sB + s) * DD + k]);  // broadcast LDS
                ull h2 = pack2(Ah[(sB + s) * DD + k]);
                acc[s][0][0] = fma2(x2, wir.x, acc[s][0][0]);
                acc[s][0][1] = fma2(x2, wir.y, acc[s][0][1]);
                acc[s][0][0] = fma2(h2, whr.x, acc[s][0][0]);
                acc[s][0][1] = fma2(h2, whr.y, acc[s][0][1]);
                acc[s][1][0] = fma2(x2, wiz.x, acc[s][1][0]);
                acc[s][1][1] = fma2(x2, wiz.y, acc[s][1][1]);
                acc[s][1][0] = fma2(h2, whz.x, acc[s][1][0]);
                acc[s][1][1] = fma2(h2, whz.y, acc[s][1][1]);
                acc[s][2][0] = fma2(x2, win.x, acc[s][2][0]);
                acc[s][2][1] = fma2(x2, win.y, acc[s][2][1]);
                acc[s][3][0] = fma2(h2, whn.x, acc[s][3][0]);
                acc[s][3][1] = fma2(h2, whn.y, acc[s][3][1]);
            }
        }
        __syncthreads();  // all GEMM reads of Ax/Ah complete

        // ---- epilogue: gates, h update (owned cells only), output dot ----
        #pragma unroll
        for (int s = 0; s < 4; ++s) {
            float hn[4];
            #pragma unroll
            for (int p = 0; p < 2; ++p) {
                #pragma unroll
                for (int half = 0; half < 2; ++half) {
                    int   uu = u0 + p * 2 + half;
                    float ar = half ? hi2(acc[s][0][p]) : lo2(acc[s][0][p]);
                    float az = half ? hi2(acc[s][1][p]) : lo2(acc[s][1][p]);
                    float axn = half ? hi2(acc[s][2][p]) : lo2(acc[s][2][p]);
                    float ahn = half ? hi2(acc[s][3][p]) : lo2(acc[s][3][p]);
                    float r = 1.f / (1.f + expf(-(ar + Bs[uu] + Bs[G3 + uu])));
                    float z = 1.f / (1.f + expf(-(az + Bs[128 + uu] + Bs[G3 + 128 + uu])));
                    float n = tanhf(axn + Bs[256 + uu] + r * (ahn + Bs[G3 + 256 + uu]));
                    float hold = Ah[(sB + s) * DD + uu];
                    hn[p * 2 + half] = (1.f - z) * n + z * hold;
                }
            }
            *(float4*)(Ah + (sB + s) * DD + u0) =
                make_float4(hn[0], hn[1], hn[2], hn[3]);

            float dot = hn[0] * wo.x + hn[1] * wo.y + hn[2] * wo.z + hn[3] * wo.w;
            #pragma unroll
            for (int off = 16; off; off >>= 1)
                dot += __shfl_xor_sync(0xffffffffu, dot, off);
            if (l == 0)
                out[(size_t)(nBase + sB + s) * LL + t] = dot + bo;
        }
        // no extra sync needed: next iter's post-load __syncthreads orders
        // these Ah writes before the next GEMM's reads.
    }
}

extern "C" void kernel_launch(void* const* d_in, const int* in_sizes, int n_in,
                              void* d_out, int out_size) {
    const float* item  = (const float*)d_in[0];
    const float* user  = (const float*)d_in[1];
    const float* W_ih  = (const float*)d_in[2];
    const float* W_hh  = (const float*)d_in[3];
    const float* b_ih  = (const float*)d_in[4];
    const float* b_hh  = (const float*)d_in[5];
    const float* W_out = (const float*)d_in[6];
    const float* b_out = (const float*)d_in[7];
    float* out = (float*)d_out;

    prep_weights<<<(DD * G3 + 255) / 256, 256>>>(W_ih, W_hh);

    size_t smem = (size_t)(2 * TN * DD + 2 * G3) * sizeof(float);  // 68.6 KB
    cudaFuncSetAttribute(gru_kernel,
                         cudaFuncAttributeMaxDynamicSharedMemorySize, (int)smem);
    gru_kernel<<<NCTA, NTHR, smem>>>(item, user, b_ih, b_hh, W_out, b_out, out);
}

// round 5
// speedup vs baseline: 3.2356x; 3.2282x over previous
#include <cuda_runtime.h>
#include <cuda_bf16.h>
#include <math.h>

// ---------------------------------------------------------------------------
// SlatewiseGRU via tensor cores: mma.sync m16n8k16 bf16, 3-term split
// (a_hi*b_hi + a_hi*b_lo + a_lo*b_hi), fp32 accumulate. Per CTA: 64 seqs.
// 16 warps; warp w owns units [w*8, w*8+8) of each gate block (r,z,nx,nh)
// across all 64 seqs (4 m-tiles) -> B-fragments reused 4x in registers.
// Weights pre-packed in fragment order by prep kernel. x split hi/lo during
// SMEM staging; h state kept as bf16 hi/lo pairs in SMEM.
// ---------------------------------------------------------------------------

#define DD   128
#define LL   32
#define NSEQ 8192
#define TN   64
#define NTHR 512
#define NCTA (NSEQ / TN)   // 128
#define SMP  136           // padded SMEM row stride in bf16 elems (68 words)

// Packed B-fragments: [wt:4 (ih_hi,ih_lo,hh_hi,hh_lo)][kt:8][ntile:48 (g*16+w)][lane:32]
__device__ uint2 g_wpack[4 * 8 * 48 * 32];

__global__ void prep_weights(const float* __restrict__ W_ih,
                             const float* __restrict__ W_hh) {
    int idx = blockIdx.x * blockDim.x + threadIdx.x;
    if (idx >= 4 * 8 * 48 * 32) return;
    int l  = idx & 31;
    int r  = idx >> 5;
    int nt = r % 48; r /= 48;
    int kt = r % 8;  r /= 8;
    int wt = r;
    const float* W = (wt < 2) ? W_ih : W_hh;
    bool lo = (wt & 1);
    int gg = nt / 16, w = nt % 16;
    int j  = gg * 128 + w * 8 + (l >> 2);     // gate row (B col n = lane>>2)
    int d0 = kt * 16 + (l & 3) * 2;           // k0 = (lane%4)*2
    unsigned short e[4];
    #pragma unroll
    for (int q = 0; q < 4; ++q) {
        int d = d0 + (q & 1) + (q >> 1) * 8;  // b0:{k0,k0+1}  b1:{k0+8,k0+9}
        float f = W[j * DD + d];
        __nv_bfloat16 h = __float2bfloat16(f);
        if (lo) h = __float2bfloat16(f - __bfloat162float(h));
        e[q] = __bfloat16_as_ushort(h);
    }
    uint2 v;
    v.x = (unsigned)e[0] | ((unsigned)e[1] << 16);
    v.y = (unsigned)e[2] | ((unsigned)e[3] << 16);
    g_wpack[idx] = v;
}

__device__ __forceinline__ unsigned pk(__nv_bfloat16 a, __nv_bfloat16 b) {
    return (unsigned)__bfloat16_as_ushort(a) | ((unsigned)__bfloat16_as_ushort(b) << 16);
}
__device__ __forceinline__ float bflo(unsigned u) {
    return __bfloat162float(__ushort_as_bfloat16((unsigned short)(u & 0xffffu)));
}
__device__ __forceinline__ float bfhi(unsigned u) {
    return __bfloat162float(__ushort_as_bfloat16((unsigned short)(u >> 16)));
}

__device__ __forceinline__ void mma16816(float* c, const unsigned* a, uint2 b) {
    asm volatile(
        "mma.sync.aligned.m16n8k16.row.col.f32.bf16.bf16.f32 "
        "{%0,%1,%2,%3}, {%4,%5,%6,%7}, {%8,%9}, {%0,%1,%2,%3};\n"
        : "+f"(c[0]), "+f"(c[1]), "+f"(c[2]), "+f"(c[3])
        : "r"(a[0]), "r"(a[1]), "r"(a[2]), "r"(a[3]), "r"(b.x), "r"(b.y));
}

extern __shared__ char smraw[];

__global__ void __launch_bounds__(NTHR, 1)
gru_mma(const float* __restrict__ item,   // [N, L, D]
        const float* __restrict__ user,   // [N, D]
        const float* __restrict__ b_ih,   // [384]
        const float* __restrict__ b_hh,   // [384]
        const float* __restrict__ W_out,  // [128]
        const float* __restrict__ b_out,  // [1]
        float* __restrict__ out)          // [N, L]
{
    unsigned short* xh = (unsigned short*)smraw;
    unsigned short* xl = xh + TN * SMP;
    unsigned short* hh = xl + TN * SMP;
    unsigned short* hl = hh + TN * SMP;
    float* outb = (float*)(hl + TN * SMP);   // [16][64]

    const int tid = threadIdx.x;
    const int w   = tid >> 5;
    const int l   = tid & 31;
    const int g   = l >> 2;   // groupID
    const int tg  = l & 3;    // thread-in-group
    const int nBase = blockIdx.x * TN;
    const int u0 = w * 8 + tg * 2;   // this thread's 2 output units (C cols)
    const int offwl = w * 32 + l;    // lane slot within wpack n-tile group

    const float br0 = b_ih[u0]         + b_hh[u0];
    const float br1 = b_ih[u0 + 1]     + b_hh[u0 + 1];
    const float bz0 = b_ih[128 + u0]   + b_hh[128 + u0];
    const float bz1 = b_ih[128 + u0 + 1] + b_hh[128 + u0 + 1];
    const float bni0 = b_ih[256 + u0], bni1 = b_ih[256 + u0 + 1];
    const float bnh0 = b_hh[256 + u0], bnh1 = b_hh[256 + u0 + 1];
    const float wo0 = W_out[u0], wo1 = W_out[u0 + 1];
    const float bo  = b_out[0];

    // h0 = user_embs; each thread initializes exactly the h cells it owns.
    #pragma unroll
    for (int mt = 0; mt < 4; ++mt)
        #pragma unroll
        for (int rh = 0; rh < 2; ++rh) {
            int row = mt * 16 + g + rh * 8;
            float2 v = *(const float2*)(user + (size_t)(nBase + row) * DD + u0);
            __nv_bfloat16 a0 = __float2bfloat16(v.x);
            __nv_bfloat16 a1 = __float2bfloat16(v.y);
            __nv_bfloat16 c0 = __float2bfloat16(v.x - __bfloat162float(a0));
            __nv_bfloat16 c1 = __float2bfloat16(v.y - __bfloat162float(a1));
            *(unsigned*)&hh[row * SMP + u0] = pk(a0, a1);
            *(unsigned*)&hl[row * SMP + u0] = pk(c0, c1);
        }

    for (int t = 0; t < LL; ++t) {
        // ---- stage x_t: load fp32, split to hi/lo bf16 in SMEM ----
        #pragma unroll
        for (int ii = 0; ii < 4; ++ii) {
            int i   = tid + ii * NTHR;       // < 2048
            int row = i >> 5;
            int c4  = (i & 31) * 4;
            float4 v = *(const float4*)(item +
                        ((size_t)(nBase + row) * LL + t) * DD + c4);
            __nv_bfloat16 h0 = __float2bfloat16(v.x), h1 = __float2bfloat16(v.y);
            __nv_bfloat16 h2 = __float2bfloat16(v.z), h3 = __float2bfloat16(v.w);
            uint2 hv, lv;
            hv.x = pk(h0, h1); hv.y = pk(h2, h3);
            lv.x = pk(__float2bfloat16(v.x - __bfloat162float(h0)),
                      __float2bfloat16(v.y - __bfloat162float(h1)));
            lv.y = pk(__float2bfloat16(v.z - __bfloat162float(h2)),
                      __float2bfloat16(v.w - __bfloat162float(h3)));
            *(uint2*)&xh[row * SMP + c4] = hv;
            *(uint2*)&xl[row * SMP + c4] = lv;
        }
        __syncthreads();   // x ready; prev-step h writes ready

        // acc[slot: r,z,nx,nh][m-tile][4 fp32]
        float acc[4][4][4];
        #pragma unroll
        for (int s = 0; s < 4; ++s)
            #pragma unroll
            for (int mt = 0; mt < 4; ++mt)
                #pragma unroll
                for (int q = 0; q < 4; ++q) acc[s][mt][q] = 0.f;

        #pragma unroll
        for (int ph = 0; ph < 2; ++ph) {   // 0: x-side (W_ih), 1: h-side (W_hh)
            const unsigned short* Ah = ph ? hh : xh;
            const unsigned short* Al = ph ? hl : xl;
            const int wth = ph ? 2 : 0;
            const int wtl = ph ? 3 : 1;
            const int ns  = ph ? 3 : 2;    // n-gate accumulator slot

            #pragma unroll 2
            for (int kt = 0; kt < 8; ++kt) {
                uint2 Bh[3], Bl[3];
                #pragma unroll
                for (int gg = 0; gg < 3; ++gg) {
                    Bh[gg] = g_wpack[(wth * 8 + kt) * 1536 + gg * 512 + offwl];
                    Bl[gg] = g_wpack[(wtl * 8 + kt) * 1536 + gg * 512 + offwl];
                }
                const int cb = kt * 16 + tg * 2;
                unsigned a[4][4];
                #pragma unroll
                for (int mt = 0; mt < 4; ++mt) {
                    int base = (mt * 16 + g) * SMP + cb;
                    a[mt][0] = *(const unsigned*)&Ah[base];
                    a[mt][1] = *(const unsigned*)&Ah[base + 8 * SMP];
                    a[mt][2] = *(const unsigned*)&Ah[base + 8];
                    a[mt][3] = *(const unsigned*)&Ah[base + 8 * SMP + 8];
                }
                #pragma unroll
                for (int gg = 0; gg < 3; ++gg) {
                    const int s = (gg < 2) ? gg : ns;
                    #pragma unroll
                    for (int mt = 0; mt < 4; ++mt) {
                        mma16816(acc[s][mt], a[mt], Bh[gg]);  // hi*Whi
                        mma16816(acc[s][mt], a[mt], Bl[gg]);  // hi*Wlo
                    }
                }
                #pragma unroll
                for (int mt = 0; mt < 4; ++mt) {
                    int base = (mt * 16 + g) * SMP + cb;
                    a[mt][0] = *(const unsigned*)&Al[base];
                    a[mt][1] = *(const unsigned*)&Al[base + 8 * SMP];
                    a[mt][2] = *(const unsigned*)&Al[base + 8];
                    a[mt][3] = *(const unsigned*)&Al[base + 8 * SMP + 8];
                }
                #pragma unroll
                for (int gg = 0; gg < 3; ++gg) {
                    const int s = (gg < 2) ? gg : ns;
                    #pragma unroll
                    for (int mt = 0; mt < 4; ++mt)
                        mma16816(acc[s][mt], a[mt], Bh[gg]);  // lo*Whi
                }
            }
        }
        __syncthreads();   // all SMEM A-fragment reads complete

        // ---- epilogue: gates, h update, output projection ----
        #pragma unroll
        for (int mt = 0; mt < 4; ++mt)
            #pragma unroll
            for (int rh = 0; rh < 2; ++rh) {
                int row = mt * 16 + g + rh * 8;
                float ar0 = acc[0][mt][rh * 2]     + br0;
                float ar1 = acc[0][mt][rh * 2 + 1] + br1;
                float az0 = acc[1][mt][rh * 2]     + bz0;
                float az1 = acc[1][mt][rh * 2 + 1] + bz1;
                float ax0 = acc[2][mt][rh * 2]     + bni0;
                float ax1 = acc[2][mt][rh * 2 + 1] + bni1;
                float ah0 = acc[3][mt][rh * 2]     + bnh0;
                float ah1 = acc[3][mt][rh * 2 + 1] + bnh1;
                float r0 = 1.f / (1.f + __expf(-ar0));
                float r1 = 1.f / (1.f + __expf(-ar1));
                float z0 = 1.f / (1.f + __expf(-az0));
                float z1 = 1.f / (1.f + __expf(-az1));
                float n0 = tanhf(ax0 + r0 * ah0);
                float n1 = tanhf(ax1 + r1 * ah1);
                // h_old reconstructed from its canonical hi+lo representation
                unsigned ohv = *(const unsigned*)&hh[row * SMP + u0];
                unsigned olv = *(const unsigned*)&hl[row * SMP + u0];
                float ho0 = bflo(ohv) + bflo(olv);
                float ho1 = bfhi(ohv) + bfhi(olv);
                float hn0 = (1.f - z0) * n0 + z0 * ho0;
                float hn1 = (1.f - z1) * n1 + z1 * ho1;
                __nv_bfloat16 p0 = __float2bfloat16(hn0);
                __nv_bfloat16 p1 = __float2bfloat16(hn1);
                *(unsigned*)&hh[row * SMP + u0] = pk(p0, p1);
                *(unsigned*)&hl[row * SMP + u0] =
                    pk(__float2bfloat16(hn0 - __bfloat162float(p0)),
                       __float2bfloat16(hn1 - __bfloat162float(p1)));
                float p = hn0 * wo0 + hn1 * wo1;
                p += __shfl_xor_sync(0xffffffffu, p, 1);
                p += __shfl_xor_sync(0xffffffffu, p, 2);
                if (tg == 0) outb[w * 64 + row] = p;
            }
        __syncthreads();   // outb complete; h writes complete

        if (tid < TN) {
            float s = bo;
            #pragma unroll
            for (int ww = 0; ww < 16; ++ww) s += outb[ww * 64 + tid];
            out[(size_t)(nBase + tid) * LL + t] = s;
        }
    }
}

extern "C" void kernel_launch(void* const* d_in, const int* in_sizes, int n_in,
                              void* d_out, int out_size) {
    const float* item  = (const float*)d_in[0];
    const float* user  = (const float*)d_in[1];
    const float* W_ih  = (const float*)d_in[2];
    const float* W_hh  = (const float*)d_in[3];
    const float* b_ih  = (const float*)d_in[4];
    const float* b_hh  = (const float*)d_in[5];
    const float* W_out = (const float*)d_in[6];
    const float* b_out = (const float*)d_in[7];
    float* out = (float*)d_out;

    prep_weights<<<(4 * 8 * 48 * 32 + 255) / 256, 256>>>(W_ih, W_hh);

    size_t smem = (size_t)(4 * TN * SMP) * sizeof(unsigned short)
                + 16 * 64 * sizeof(float);   // 69632 + 4096 = 73728
    cudaFuncSetAttribute(gru_mma,
                         cudaFuncAttributeMaxDynamicSharedMemorySize, (int)smem);
    gru_mma<<<NCTA, NTHR, smem>>>(item, user, b_ih, b_hh, W_out, b_out, out);
}

// round 6
// speedup vs baseline: 3.8882x; 1.2017x over previous
#include <cuda_runtime.h>
#include <cuda_bf16.h>
#include <math.h>

// ---------------------------------------------------------------------------
// SlatewiseGRU via tensor cores: mma.sync m16n8k16 bf16, 3-term split
// (hi*hi + hi*lo + lo*hi), fp32 accumulate. Per CTA: 64 seqs, 16 warps.
// R5: ldmatrix.x4 A-fragments, fully-unrolled kt loop (ptxas pipelines B
// LDGs), x_{t+1} register prefetch under the MMA phase, __expf-based
// sigmoid/tanh epilogue, 2 barriers/step.
// ---------------------------------------------------------------------------

#define DD   128
#define LL   32
#define NSEQ 8192
#define TN   64
#define NTHR 512
#define NCTA (NSEQ / TN)   // 128
#define SMP  136           // padded SMEM row stride (bf16 elems); row = 272 B

// Packed B-fragments: [wt:4 (ih_hi,ih_lo,hh_hi,hh_lo)][kt:8][ntile:48][lane:32]
__device__ uint2 g_wpack[4 * 8 * 48 * 32];

__global__ void prep_weights(const float* __restrict__ W_ih,
                             const float* __restrict__ W_hh) {
    int idx = blockIdx.x * blockDim.x + threadIdx.x;
    if (idx >= 4 * 8 * 48 * 32) return;
    int l  = idx & 31;
    int r  = idx >> 5;
    int nt = r % 48; r /= 48;
    int kt = r % 8;  r /= 8;
    int wt = r;
    const float* W = (wt < 2) ? W_ih : W_hh;
    bool lo = (wt & 1);
    int gg = nt / 16, w = nt % 16;
    int j  = gg * 128 + w * 8 + (l >> 2);
    int d0 = kt * 16 + (l & 3) * 2;
    unsigned short e[4];
    #pragma unroll
    for (int q = 0; q < 4; ++q) {
        int d = d0 + (q & 1) + (q >> 1) * 8;
        float f = W[j * DD + d];
        __nv_bfloat16 h = __float2bfloat16(f);
        if (lo) h = __float2bfloat16(f - __bfloat162float(h));
        e[q] = __bfloat16_as_ushort(h);
    }
    uint2 v;
    v.x = (unsigned)e[0] | ((unsigned)e[1] << 16);
    v.y = (unsigned)e[2] | ((unsigned)e[3] << 16);
    g_wpack[idx] = v;
}

__device__ __forceinline__ unsigned pk(__nv_bfloat16 a, __nv_bfloat16 b) {
    return (unsigned)__bfloat16_as_ushort(a) | ((unsigned)__bfloat16_as_ushort(b) << 16);
}
__device__ __forceinline__ float bflo(unsigned u) {
    return __bfloat162float(__ushort_as_bfloat16((unsigned short)(u & 0xffffu)));
}
__device__ __forceinline__ float bfhi(unsigned u) {
    return __bfloat162float(__ushort_as_bfloat16((unsigned short)(u >> 16)));
}

__device__ __forceinline__ void mma16816(float* c, const unsigned* a, uint2 b) {
    asm volatile(
        "mma.sync.aligned.m16n8k16.row.col.f32.bf16.bf16.f32 "
        "{%0,%1,%2,%3}, {%4,%5,%6,%7}, {%8,%9}, {%0,%1,%2,%3};\n"
        : "+f"(c[0]), "+f"(c[1]), "+f"(c[2]), "+f"(c[3])
        : "r"(a[0]), "r"(a[1]), "r"(a[2]), "r"(a[3]), "r"(b.x), "r"(b.y));
}

__device__ __forceinline__ void ldsm4(unsigned* r, unsigned addr) {
    asm volatile("ldmatrix.sync.aligned.m8n8.x4.shared.b16 {%0,%1,%2,%3}, [%4];"
                 : "=r"(r[0]), "=r"(r[1]), "=r"(r[2]), "=r"(r[3]) : "r"(addr));
}

__device__ __forceinline__ float sigm(float x) {
    return __fdividef(1.f, 1.f + __expf(-x));
}
__device__ __forceinline__ float tanhfast(float x) {
    return 1.f - __fdividef(2.f, __expf(2.f * x) + 1.f);
}

extern __shared__ char smraw[];

__global__ void __launch_bounds__(NTHR, 1)
gru_mma(const float* __restrict__ item,   // [N, L, D]
        const float* __restrict__ user,   // [N, D]
        const float* __restrict__ b_ih,   // [384]
        const float* __restrict__ b_hh,   // [384]
        const float* __restrict__ W_out,  // [128]
        const float* __restrict__ b_out,  // [1]
        float* __restrict__ out)          // [N, L]
{
    unsigned short* xh = (unsigned short*)smraw;
    unsigned short* xl = xh + TN * SMP;
    unsigned short* hh = xl + TN * SMP;
    unsigned short* hl = hh + TN * SMP;
    float* outb = (float*)(hl + TN * SMP);   // [16][64]

    const int tid = threadIdx.x;
    const int w   = tid >> 5;
    const int l   = tid & 31;
    const int g   = l >> 2;
    const int tg  = l & 3;
    const int nBase = blockIdx.x * TN;
    const int u0 = w * 8 + tg * 2;
    const int offwl = w * 32 + l;

    // ldmatrix per-thread base addresses (shared-space byte addrs)
    const int rowsel = l & 15;
    const int halfc  = l >> 4;
    const unsigned lmOff = (unsigned)((rowsel * SMP + halfc * 8) * 2);
    const unsigned xhA = (unsigned)__cvta_generic_to_shared(xh) + lmOff;
    const unsigned xlA = (unsigned)__cvta_generic_to_shared(xl) + lmOff;
    const unsigned hhA = (unsigned)__cvta_generic_to_shared(hh) + lmOff;
    const unsigned hlA = (unsigned)__cvta_generic_to_shared(hl) + lmOff;

    const float br0 = b_ih[u0]           + b_hh[u0];
    const float br1 = b_ih[u0 + 1]       + b_hh[u0 + 1];
    const float bz0 = b_ih[128 + u0]     + b_hh[128 + u0];
    const float bz1 = b_ih[128 + u0 + 1] + b_hh[128 + u0 + 1];
    const float bni0 = b_ih[256 + u0], bni1 = b_ih[256 + u0 + 1];
    const float bnh0 = b_hh[256 + u0], bnh1 = b_hh[256 + u0 + 1];
    const float wo0 = W_out[u0], wo1 = W_out[u0 + 1];
    const float bo  = b_out[0];

    // h0 = user_embs; owner-thread init (hi/lo split)
    #pragma unroll
    for (int mt = 0; mt < 4; ++mt)
        #pragma unroll
        for (int rh = 0; rh < 2; ++rh) {
            int row = mt * 16 + g + rh * 8;
            float2 v = *(const float2*)(user + (size_t)(nBase + row) * DD + u0);
            __nv_bfloat16 a0 = __float2bfloat16(v.x);
            __nv_bfloat16 a1 = __float2bfloat16(v.y);
            *(unsigned*)&hh[row * SMP + u0] = pk(a0, a1);
            *(unsigned*)&hl[row * SMP + u0] =
                pk(__float2bfloat16(v.x - __bfloat162float(a0)),
                   __float2bfloat16(v.y - __bfloat162float(a1)));
        }

    // staging coordinates for this thread (4 float4 rows/cols per step)
    int srow[4], scol[4];
    #pragma unroll
    for (int ii = 0; ii < 4; ++ii) {
        int i = tid + ii * NTHR;
        srow[ii] = i >> 5;
        scol[ii] = (i & 31) * 4;
    }

    // prologue: prefetch x_0
    float4 xr[4];
    #pragma unroll
    for (int ii = 0; ii < 4; ++ii)
        xr[ii] = *(const float4*)(item +
                   ((size_t)(nBase + srow[ii]) * LL + 0) * DD + scol[ii]);

    for (int t = 0; t < LL; ++t) {
        // ---- store prefetched x_t into SMEM (hi/lo split) ----
        #pragma unroll
        for (int ii = 0; ii < 4; ++ii) {
            float4 v = xr[ii];
            __nv_bfloat16 h0 = __float2bfloat16(v.x), h1 = __float2bfloat16(v.y);
            __nv_bfloat16 h2 = __float2bfloat16(v.z), h3 = __float2bfloat16(v.w);
            uint2 hv, lv;
            hv.x = pk(h0, h1); hv.y = pk(h2, h3);
            lv.x = pk(__float2bfloat16(v.x - __bfloat162float(h0)),
                      __float2bfloat16(v.y - __bfloat162float(h1)));
            lv.y = pk(__float2bfloat16(v.z - __bfloat162float(h2)),
                      __float2bfloat16(v.w - __bfloat162float(h3)));
            *(uint2*)&xh[srow[ii] * SMP + scol[ii]] = hv;
            *(uint2*)&xl[srow[ii] * SMP + scol[ii]] = lv;
        }
        __syncthreads();   // x_t, h(t-1) writes, outb(t-1) all visible

        // ---- finish output of step t-1 (overlaps with MMA issue below) ----
        if (t > 0 && tid < TN) {
            float s = bo;
            #pragma unroll
            for (int ww = 0; ww < 16; ++ww) s += outb[ww * 64 + tid];
            out[(size_t)(nBase + tid) * LL + (t - 1)] = s;
        }

        float acc[4][4][4];
        #pragma unroll
        for (int s = 0; s < 4; ++s)
            #pragma unroll
            for (int mt = 0; mt < 4; ++mt)
                #pragma unroll
                for (int q = 0; q < 4; ++q) acc[s][mt][q] = 0.f;

        #pragma unroll
        for (int ph = 0; ph < 2; ++ph) {
            const unsigned aH = ph ? hhA : xhA;
            const unsigned aL = ph ? hlA : xlA;
            const int wth = ph ? 2 : 0;
            const int wtl = ph ? 3 : 1;
            const int ns  = ph ? 3 : 2;

            #pragma unroll
            for (int kt = 0; kt < 8; ++kt) {
                uint2 Bh[3], Bl[3];
                #pragma unroll
                for (int gg = 0; gg < 3; ++gg) {
                    Bh[gg] = g_wpack[(wth * 8 + kt) * 1536 + gg * 512 + offwl];
                    Bl[gg] = g_wpack[(wtl * 8 + kt) * 1536 + gg * 512 + offwl];
                }
                unsigned a[4][4];
                #pragma unroll
                for (int mt = 0; mt < 4; ++mt)
                    ldsm4(a[mt], aH + mt * (16 * SMP * 2) + kt * 32);
                #pragma unroll
                for (int gg = 0; gg < 3; ++gg) {
                    const int s = (gg < 2) ? gg : ns;
                    #pragma unroll
                    for (int mt = 0; mt < 4; ++mt) {
                        mma16816(acc[s][mt], a[mt], Bh[gg]);
                        mma16816(acc[s][mt], a[mt], Bl[gg]);
                    }
                }
                #pragma unroll
                for (int mt = 0; mt < 4; ++mt)
                    ldsm4(a[mt], aL + mt * (16 * SMP * 2) + kt * 32);
                #pragma unroll
                for (int gg = 0; gg < 3; ++gg) {
                    const int s = (gg < 2) ? gg : ns;
                    #pragma unroll
                    for (int mt = 0; mt < 4; ++mt)
                        mma16816(acc[s][mt], a[mt], Bh[gg]);
                }
            }
        }

        // ---- prefetch x_{t+1} while MMAs drain ----
        if (t < LL - 1) {
            #pragma unroll
            for (int ii = 0; ii < 4; ++ii)
                xr[ii] = *(const float4*)(item +
                           ((size_t)(nBase + srow[ii]) * LL + (t + 1)) * DD + scol[ii]);
        }
        __syncthreads();   // all SMEM A reads complete

        // ---- epilogue: gates, h update, output partials ----
        #pragma unroll
        for (int mt = 0; mt < 4; ++mt)
            #pragma unroll
            for (int rh = 0; rh < 2; ++rh) {
                int row = mt * 16 + g + rh * 8;
                float r0 = sigm(acc[0][mt][rh * 2]     + br0);
                float r1 = sigm(acc[0][mt][rh * 2 + 1] + br1);
                float z0 = sigm(acc[1][mt][rh * 2]     + bz0);
                float z1 = sigm(acc[1][mt][rh * 2 + 1] + bz1);
                float n0 = tanhfast(acc[2][mt][rh * 2]     + bni0
                                    + r0 * (acc[3][mt][rh * 2]     + bnh0));
                float n1 = tanhfast(acc[2][mt][rh * 2 + 1] + bni1
                                    + r1 * (acc[3][mt][rh * 2 + 1] + bnh1));
                unsigned ohv = *(const unsigned*)&hh[row * SMP + u0];
                unsigned olv = *(const unsigned*)&hl[row * SMP + u0];
                float ho0 = bflo(ohv) + bflo(olv);
                float ho1 = bfhi(ohv) + bfhi(olv);
                float hn0 = (1.f - z0) * n0 + z0 * ho0;
                float hn1 = (1.f - z1) * n1 + z1 * ho1;
                __nv_bfloat16 p0 = __float2bfloat16(hn0);
                __nv_bfloat16 p1 = __float2bfloat16(hn1);
                *(unsigned*)&hh[row * SMP + u0] = pk(p0, p1);
                *(unsigned*)&hl[row * SMP + u0] =
                    pk(__float2bfloat16(hn0 - __bfloat162float(p0)),
                       __float2bfloat16(hn1 - __bfloat162float(p1)));
                float p = hn0 * wo0 + hn1 * wo1;
                p += __shfl_xor_sync(0xffffffffu, p, 1);
                p += __shfl_xor_sync(0xffffffffu, p, 2);
                if (tg == 0) outb[w * 64 + row] = p;
            }
        // next iteration's first barrier covers outb/h visibility
    }

    __syncthreads();
    if (tid < TN) {
        float s = bo;
        #pragma unroll
        for (int ww = 0; ww < 16; ++ww) s += outb[ww * 64 + tid];
        out[(size_t)(nBase + tid) * LL + (LL - 1)] = s;
    }
}

extern "C" void kernel_launch(void* const* d_in, const int* in_sizes, int n_in,
                              void* d_out, int out_size) {
    const float* item  = (const float*)d_in[0];
    const float* user  = (const float*)d_in[1];
    const float* W_ih  = (const float*)d_in[2];
    const float* W_hh  = (const float*)d_in[3];
    const float* b_ih  = (const float*)d_in[4];
    const float* b_hh  = (const float*)d_in[5];
    const float* W_out = (const float*)d_in[6];
    const float* b_out = (const float*)d_in[7];
    float* out = (float*)d_out;

    prep_weights<<<(4 * 8 * 48 * 32 + 255) / 256, 256>>>(W_ih, W_hh);

    size_t smem = (size_t)(4 * TN * SMP) * sizeof(unsigned short)
                + 16 * 64 * sizeof(float);   // 69632 + 4096 = 73728
    cudaFuncSetAttribute(gru_mma,
                         cudaFuncAttributeMaxDynamicSharedMemorySize, (int)smem);
    gru_mma<<<NCTA, NTHR, smem>>>(item, user, b_ih, b_hh, W_out, b_out, out);
}

// round 7
// speedup vs baseline: 3.8948x; 1.0017x over previous
#include <cuda_runtime.h>
#include <cuda_bf16.h>
#include <math.h>

// ---------------------------------------------------------------------------
// SlatewiseGRU via tensor cores: mma.sync m16n8k16 bf16, 3-term split
// (hi*hi + hi*lo + lo*hi), fp32 accumulate.
// R6: 2 CTAs/SM (256 thr, 32 seqs, grid=256, launch_bounds(256,2)) so two
// independent CTAs overlap: one CTA's MMAs fill the tensor pipe while the
// other sits in barriers/epilogue. Biases in SMEM to hold regs <= 128.
// ---------------------------------------------------------------------------

#define DD   128
#define LL   32
#define NSEQ 8192
#define TN   32
#define NTHR 256
#define NCTA (NSEQ / TN)   // 256
#define SMP  136           // padded SMEM row stride (bf16 elems); row = 272 B

// Packed B-fragments: [wt:4 (ih_hi,ih_lo,hh_hi,hh_lo)][kt:8][ntile:48][lane:32]
__device__ uint2 g_wpack[4 * 8 * 48 * 32];

__global__ void prep_weights(const float* __restrict__ W_ih,
                             const float* __restrict__ W_hh) {
    int idx = blockIdx.x * blockDim.x + threadIdx.x;
    if (idx >= 4 * 8 * 48 * 32) return;
    int l  = idx & 31;
    int r  = idx >> 5;
    int nt = r % 48; r /= 48;
    int kt = r % 8;  r /= 8;
    int wt = r;
    const float* W = (wt < 2) ? W_ih : W_hh;
    bool lo = (wt & 1);
    int gg = nt / 16, w = nt % 16;
    int j  = gg * 128 + w * 8 + (l >> 2);
    int d0 = kt * 16 + (l & 3) * 2;
    unsigned short e[4];
    #pragma unroll
    for (int q = 0; q < 4; ++q) {
        int d = d0 + (q & 1) + (q >> 1) * 8;
        float f = W[j * DD + d];
        __nv_bfloat16 h = __float2bfloat16(f);
        if (lo) h = __float2bfloat16(f - __bfloat162float(h));
        e[q] = __bfloat16_as_ushort(h);
    }
    uint2 v;
    v.x = (unsigned)e[0] | ((unsigned)e[1] << 16);
    v.y = (unsigned)e[2] | ((unsigned)e[3] << 16);
    g_wpack[idx] = v;
}

__device__ __forceinline__ unsigned pk(__nv_bfloat16 a, __nv_bfloat16 b) {
    return (unsigned)__bfloat16_as_ushort(a) | ((unsigned)__bfloat16_as_ushort(b) << 16);
}
__device__ __forceinline__ float bflo(unsigned u) {
    return __bfloat162float(__ushort_as_bfloat16((unsigned short)(u & 0xffffu)));
}
__device__ __forceinline__ float bfhi(unsigned u) {
    return __bfloat162float(__ushort_as_bfloat16((unsigned short)(u >> 16)));
}

__device__ __forceinline__ void mma16816(float* c, const unsigned* a, uint2 b) {
    asm volatile(
        "mma.sync.aligned.m16n8k16.row.col.f32.bf16.bf16.f32 "
        "{%0,%1,%2,%3}, {%4,%5,%6,%7}, {%8,%9}, {%0,%1,%2,%3};\n"
        : "+f"(c[0]), "+f"(c[1]), "+f"(c[2]), "+f"(c[3])
        : "r"(a[0]), "r"(a[1]), "r"(a[2]), "r"(a[3]), "r"(b.x), "r"(b.y));
}

__device__ __forceinline__ void ldsm4(unsigned* r, unsigned addr) {
    asm volatile("ldmatrix.sync.aligned.m8n8.x4.shared.b16 {%0,%1,%2,%3}, [%4];"
                 : "=r"(r[0]), "=r"(r[1]), "=r"(r[2]), "=r"(r[3]) : "r"(addr));
}

__device__ __forceinline__ float sigm(float x) {
    return __fdividef(1.f, 1.f + __expf(-x));
}
__device__ __forceinline__ float tanhfast(float x) {
    return 1.f - __fdividef(2.f, __expf(2.f * x) + 1.f);
}

extern __shared__ char smraw[];

__global__ void __launch_bounds__(NTHR, 2)
gru_mma(const float* __restrict__ item,   // [N, L, D]
        const float* __restrict__ user,   // [N, D]
        const float* __restrict__ b_ih,   // [384]
        const float* __restrict__ b_hh,   // [384]
        const float* __restrict__ W_out,  // [128]
        const float* __restrict__ b_out,  // [1]
        float* __restrict__ out)          // [N, L]
{
    unsigned short* xh = (unsigned short*)smraw;
    unsigned short* xl = xh + TN * SMP;
    unsigned short* hh = xl + TN * SMP;
    unsigned short* hl = hh + TN * SMP;
    float* outb = (float*)(hl + TN * SMP);   // [8][32]
    float* Bs   = outb + 8 * TN;             // [512]: rz combined | n_ih | n_hh

    const int tid = threadIdx.x;
    const int w   = tid >> 5;   // 8 warps
    const int l   = tid & 31;
    const int g   = l >> 2;
    const int tg  = l & 3;
    const int nBase = blockIdx.x * TN;

    // Biases -> SMEM: [0:256) = b_ih+b_hh for r,z; [256:384) = b_ih n;
    // [384:512) = b_hh n.
    for (int i = tid; i < 512; i += NTHR) {
        float v;
        if (i < 256)      v = b_ih[i] + b_hh[i];
        else if (i < 384) v = b_ih[i];          // 256 + (i-256)
        else              v = b_hh[i - 128];    // 256 + (i-384)
        Bs[i] = v;
    }

    // ldmatrix per-thread base addresses
    const int rowsel = l & 15;
    const int halfc  = l >> 4;
    const unsigned lmOff = (unsigned)((rowsel * SMP + halfc * 8) * 2);
    const unsigned xhA = (unsigned)__cvta_generic_to_shared(xh) + lmOff;
    const unsigned xlA = (unsigned)__cvta_generic_to_shared(xl) + lmOff;
    const unsigned hhA = (unsigned)__cvta_generic_to_shared(hh) + lmOff;
    const unsigned hlA = (unsigned)__cvta_generic_to_shared(hl) + lmOff;

    // this thread's output units: two groups of 2, in n8-subtiles nt=0,1
    const int ua = w * 16 + tg * 2;       // nt = 0
    const int ub = ua + 8;                // nt = 1
    float2 woA = *(const float2*)(W_out + ua);
    float2 woB = *(const float2*)(W_out + ub);
    const float bo = b_out[0];

    // h0 = user_embs; owner-thread init (hi/lo split)
    #pragma unroll
    for (int mt = 0; mt < 2; ++mt)
        #pragma unroll
        for (int rh = 0; rh < 2; ++rh) {
            int row = mt * 16 + g + rh * 8;
            #pragma unroll
            for (int nt = 0; nt < 2; ++nt) {
                int u = (nt ? ub : ua);
                float2 v = *(const float2*)(user + (size_t)(nBase + row) * DD + u);
                __nv_bfloat16 a0 = __float2bfloat16(v.x);
                __nv_bfloat16 a1 = __float2bfloat16(v.y);
                *(unsigned*)&hh[row * SMP + u] = pk(a0, a1);
                *(unsigned*)&hl[row * SMP + u] =
                    pk(__float2bfloat16(v.x - __bfloat162float(a0)),
                       __float2bfloat16(v.y - __bfloat162float(a1)));
            }
        }

    // staging coordinates (4 float4 per thread per step: 32 rows x 32 float4)
    int srow[4], scol[4];
    #pragma unroll
    for (int ii = 0; ii < 4; ++ii) {
        int i = tid + ii * NTHR;
        srow[ii] = i >> 5;
        scol[ii] = (i & 31) * 4;
    }

    // prologue: prefetch x_0
    float4 xr[4];
    #pragma unroll
    for (int ii = 0; ii < 4; ++ii)
        xr[ii] = *(const float4*)(item +
                   ((size_t)(nBase + srow[ii]) * LL + 0) * DD + scol[ii]);

    for (int t = 0; t < LL; ++t) {
        // ---- store prefetched x_t into SMEM (hi/lo split) ----
        #pragma unroll
        for (int ii = 0; ii < 4; ++ii) {
            float4 v = xr[ii];
            __nv_bfloat16 h0 = __float2bfloat16(v.x), h1 = __float2bfloat16(v.y);
            __nv_bfloat16 h2 = __float2bfloat16(v.z), h3 = __float2bfloat16(v.w);
            uint2 hv, lv;
            hv.x = pk(h0, h1); hv.y = pk(h2, h3);
            lv.x = pk(__float2bfloat16(v.x - __bfloat162float(h0)),
                      __float2bfloat16(v.y - __bfloat162float(h1)));
            lv.y = pk(__float2bfloat16(v.z - __bfloat162float(h2)),
                      __float2bfloat16(v.w - __bfloat162float(h3)));
            *(uint2*)&xh[srow[ii] * SMP + scol[ii]] = hv;
            *(uint2*)&xl[srow[ii] * SMP + scol[ii]] = lv;
        }
        __syncthreads();   // x_t, h(t-1) writes, outb(t-1) all visible

        // ---- finish output of step t-1 ----
        if (t > 0 && tid < TN) {
            float s = bo;
            #pragma unroll
            for (int ww = 0; ww < 8; ++ww) s += outb[ww * TN + tid];
            out[(size_t)(nBase + tid) * LL + (t - 1)] = s;
        }

        // acc[slot r,z,nx,nh][mt:2][nt:2][4]
        float acc[4][2][2][4];
        #pragma unroll
        for (int s = 0; s < 4; ++s)
            #pragma unroll
            for (int mt = 0; mt < 2; ++mt)
                #pragma unroll
                for (int nt = 0; nt < 2; ++nt)
                    #pragma unroll
                    for (int q = 0; q < 4; ++q) acc[s][mt][nt][q] = 0.f;

        #pragma unroll
        for (int ph = 0; ph < 2; ++ph) {
            const unsigned aH = ph ? hhA : xhA;
            const unsigned aL = ph ? hlA : xlA;
            const int wth = ph ? 2 : 0;
            const int wtl = ph ? 3 : 1;
            const int ns  = ph ? 3 : 2;

            #pragma unroll
            for (int kt = 0; kt < 8; ++kt) {
                uint2 Bh[3][2], Bl[3][2];
                #pragma unroll
                for (int gg = 0; gg < 3; ++gg)
                    #pragma unroll
                    for (int nt = 0; nt < 2; ++nt) {
                        int off = (gg * 16 + 2 * w + nt) * 32 + l;
                        Bh[gg][nt] = g_wpack[(wth * 8 + kt) * 1536 + off];
                        Bl[gg][nt] = g_wpack[(wtl * 8 + kt) * 1536 + off];
                    }
                unsigned a[2][4];
                #pragma unroll
                for (int mt = 0; mt < 2; ++mt)
                    ldsm4(a[mt], aH + mt * (16 * SMP * 2) + kt * 32);
                #pragma unroll
                for (int gg = 0; gg < 3; ++gg) {
                    const int s = (gg < 2) ? gg : ns;
                    #pragma unroll
                    for (int nt = 0; nt < 2; ++nt)
                        #pragma unroll
                        for (int mt = 0; mt < 2; ++mt) {
                            mma16816(acc[s][mt][nt], a[mt], Bh[gg][nt]);
                            mma16816(acc[s][mt][nt], a[mt], Bl[gg][nt]);
                        }
                }
                #pragma unroll
                for (int mt = 0; mt < 2; ++mt)
                    ldsm4(a[mt], aL + mt * (16 * SMP * 2) + kt * 32);
                #pragma unroll
                for (int gg = 0; gg < 3; ++gg) {
                    const int s = (gg < 2) ? gg : ns;
                    #pragma unroll
                    for (int nt = 0; nt < 2; ++nt)
                        #pragma unroll
                        for (int mt = 0; mt < 2; ++mt)
                            mma16816(acc[s][mt][nt], a[mt], Bh[gg][nt]);
                }
            }
        }

        // ---- prefetch x_{t+1} while MMAs drain ----
        if (t < LL - 1) {
            #pragma unroll
            for (int ii = 0; ii < 4; ++ii)
                xr[ii] = *(const float4*)(item +
                           ((size_t)(nBase + srow[ii]) * LL + (t + 1)) * DD + scol[ii]);
        }
        __syncthreads();   // all SMEM A reads complete

        // ---- epilogue: gates, h update, output partials ----
        #pragma unroll
        for (int mt = 0; mt < 2; ++mt)
            #pragma unroll
            for (int rh = 0; rh < 2; ++rh) {
                int row = mt * 16 + g + rh * 8;
                float p = 0.f;
                #pragma unroll
                for (int nt = 0; nt < 2; ++nt) {
                    int u = (nt ? ub : ua);
                    float wox = nt ? woB.x : woA.x;
                    float woy = nt ? woB.y : woA.y;
                    float r0 = sigm(acc[0][mt][nt][rh * 2]     + Bs[u]);
                    float r1 = sigm(acc[0][mt][nt][rh * 2 + 1] + Bs[u + 1]);
                    float z0 = sigm(acc[1][mt][nt][rh * 2]     + Bs[128 + u]);
                    float z1 = sigm(acc[1][mt][nt][rh * 2 + 1] + Bs[128 + u + 1]);
                    float n0 = tanhfast(acc[2][mt][nt][rh * 2] + Bs[256 + u]
                               + r0 * (acc[3][mt][nt][rh * 2]  + Bs[384 + u]));
                    float n1 = tanhfast(acc[2][mt][nt][rh * 2 + 1] + Bs[256 + u + 1]
                               + r1 * (acc[3][mt][nt][rh * 2 + 1]  + Bs[384 + u + 1]));
                    unsigned ohv = *(const unsigned*)&hh[row * SMP + u];
                    unsigned olv = *(const unsigned*)&hl[row * SMP + u];
                    float ho0 = bflo(ohv) + bflo(olv);
                    float ho1 = bfhi(ohv) + bfhi(olv);
                    float hn0 = (1.f - z0) * n0 + z0 * ho0;
                    float hn1 = (1.f - z1) * n1 + z1 * ho1;
                    __nv_bfloat16 p0 = __float2bfloat16(hn0);
                    __nv_bfloat16 p1 = __float2bfloat16(hn1);
                    *(unsigned*)&hh[row * SMP + u] = pk(p0, p1);
                    *(unsigned*)&hl[row * SMP + u] =
                        pk(__float2bfloat16(hn0 - __bfloat162float(p0)),
                           __float2bfloat16(hn1 - __bfloat162float(p1)));
                    p += hn0 * wox + hn1 * woy;
                }
                p += __shfl_xor_sync(0xffffffffu, p, 1);
                p += __shfl_xor_sync(0xffffffffu, p, 2);
                if (tg == 0) outb[w * TN + row] = p;
            }
        // next iteration's first barrier covers outb/h visibility
    }

    __syncthreads();
    if (tid < TN) {
        float s = bo;
        #pragma unroll
        for (int ww = 0; ww < 8; ++ww) s += outb[ww * TN + tid];
        out[(size_t)(nBase + tid) * LL + (LL - 1)] = s;
    }
}

extern "C" void kernel_launch(void* const* d_in, const int* in_sizes, int n_in,
                              void* d_out, int out_size) {
    const float* item  = (const float*)d_in[0];
    const float* user  = (const float*)d_in[1];
    const float* W_ih  = (const float*)d_in[2];
    const float* W_hh  = (const float*)d_in[3];
    const float* b_ih  = (const float*)d_in[4];
    const float* b_hh  = (const float*)d_in[5];
    const float* W_out = (const float*)d_in[6];
    const float* b_out = (const float*)d_in[7];
    float* out = (float*)d_out;

    prep_weights<<<(4 * 8 * 48 * 32 + 255) / 256, 256>>>(W_ih, W_hh);

    size_t smem = (size_t)(4 * TN * SMP) * sizeof(unsigned short)
                + 8 * TN * sizeof(float)        // outb
                + 512 * sizeof(float);          // biases
    // 34816 + 1024 + 2048 = 37888 B per CTA -> 75776 B per SM at 2 CTAs
    cudaFuncSetAttribute(gru_mma,
                         cudaFuncAttributeMaxDynamicSharedMemorySize, (int)smem);
    gru_mma<<<NCTA, NTHR, smem>>>(item, user, b_ih, b_hh, W_out, b_out, out);
}